// round 2
// baseline (speedup 1.0000x reference)
#include <cuda_runtime.h>
#include <cstdint>

// ---------------- static device scratch (globals are the sanctioned scratch) ----------------
#define N_  32
#define C_  256
#define H_  56
#define W_  56
#define PH_ 58
#define PW_ 58
#define PIX_ (H_*W_)                 // 3136
#define M_   (N_*PIX_)               // 100352 pixels per conv
#define TOT_ (N_*C_*PIX_)            // 25690112 elements
#define NW_  4                       // u64 words per pixel (256 ch)

__device__ unsigned long long g_Xp[(size_t)N_*PH_*PW_*NW_];   // packed padded input  (3.44 MB)
__device__ unsigned long long g_Ap[(size_t)N_*PH_*PW_*NW_];   // packed padded act2   (3.44 MB)
__device__ unsigned long long g_W1[9*C_*NW_];                 // packed weights conv1
__device__ unsigned long long g_W2[9*C_*NW_];
__device__ int   g_c1[9*C_];                                  // border corrections [type][cout]
__device__ int   g_c2[9*C_];
__device__ short g_S1[TOT_];                                  // conv1 raw sums NCHW (51.4 MB)
__device__ short g_S2[TOT_];
__device__ long long g_sum1[C_], g_sq1[C_], g_sum2[C_], g_sq2[C_];
__device__ float g_a1[C_], g_b1[C_], g_a2[C_], g_b2[C_];

// ---------------- tiny helpers ----------------
__global__ void zero_stats_k() {
    int i = threadIdx.x;
    g_sum1[i] = 0; g_sq1[i] = 0; g_sum2[i] = 0; g_sq2[i] = 0;
}

// pack weights: w [O=256][I=256][3][3] float -> Wp[t][cout][4] u64 (bit=1 means +1)
__global__ void pack_w_k(const float* __restrict__ w, unsigned long long* __restrict__ Wp) {
    int t = blockIdx.x;            // 0..8
    int c = threadIdx.x;           // cout 0..255
    int ky = t / 3, kx = t % 3;
    for (int j = 0; j < NW_; ++j) {
        unsigned long long bits = 0ull;
        #pragma unroll 4
        for (int cl = 0; cl < 64; ++cl) {
            int cin = j * 64 + cl;
            float v = w[(((size_t)c * C_ + cin) * 3 + ky) * 3 + kx];
            bits |= (unsigned long long)(v > 0.0f) << cl;
        }
        Wp[((size_t)t * C_ + c) * NW_ + j] = bits;
    }
}

// border-type corrections: corr[type][c] = sum over invalid taps of (256 - 2*popc(w_tap))
__global__ void corr_w_k(const unsigned long long* __restrict__ Wp, int* __restrict__ corr) {
    int c = threadIdx.x;
    int pc[9];
    #pragma unroll
    for (int t = 0; t < 9; ++t) {
        int s = 0;
        #pragma unroll
        for (int j = 0; j < NW_; ++j) s += __popcll(Wp[((size_t)t * C_ + c) * NW_ + j]);
        pc[t] = s;
    }
    for (int type = 0; type < 9; ++type) {
        int rt = type / 3, ct = type % 3;
        int s = 0;
        #pragma unroll
        for (int ky = 0; ky < 3; ++ky)
            #pragma unroll
            for (int kx = 0; kx < 3; ++kx) {
                bool rinv = (rt == 0 && ky == 0) || (rt == 2 && ky == 2);
                bool cinv = (ct == 0 && kx == 0) || (ct == 2 && kx == 2);
                if (rinv || cinv) s += 256 - 2 * pc[ky * 3 + kx];
            }
        corr[type * C_ + c] = s;
    }
}

// pack input x (NCHW float) -> padded packed bitplanes, halo = 0 bits
__global__ void pack_x_k(const float* __restrict__ x, unsigned long long* __restrict__ Xp) {
    int px = threadIdx.x;   // 0..57
    int j  = threadIdx.y;   // 0..3
    int py = blockIdx.x;    // 0..57
    int n  = blockIdx.y;    // 0..31
    size_t oidx = (((size_t)n * PH_ + py) * PW_ + px) * NW_ + j;
    if (px == 0 || px == PW_ - 1 || py == 0 || py == PH_ - 1) { Xp[oidx] = 0ull; return; }
    int ix = px - 1, iy = py - 1;
    const float* xp = x + (((size_t)n * C_ + j * 64) * H_ + iy) * W_ + ix;
    unsigned long long bits = 0ull;
    #pragma unroll 8
    for (int cl = 0; cl < 64; ++cl)
        bits |= (unsigned long long)(xp[(size_t)cl * PIX_] > 0.0f) << cl;
    Xp[oidx] = bits;
}

// threshold conv1 sums -> packed padded bitplanes for conv2: bit = (a[c]*S + b[c] > 0)
__global__ void thresh_pack_k(const short* __restrict__ S,
                              const float* __restrict__ a, const float* __restrict__ b,
                              unsigned long long* __restrict__ Ap) {
    int px = threadIdx.x, j = threadIdx.y;
    int py = blockIdx.x, n = blockIdx.y;
    size_t oidx = (((size_t)n * PH_ + py) * PW_ + px) * NW_ + j;
    if (px == 0 || px == PW_ - 1 || py == 0 || py == PH_ - 1) { Ap[oidx] = 0ull; return; }
    int ix = px - 1, iy = py - 1;
    const short* sp = S + (((size_t)n * C_ + j * 64) * H_ + iy) * W_ + ix;
    unsigned long long bits = 0ull;
    #pragma unroll 8
    for (int cl = 0; cl < 64; ++cl) {
        int c = j * 64 + cl;
        float z = __ldg(&a[c]) * (float)sp[(size_t)cl * PIX_] + __ldg(&b[c]);
        bits |= (unsigned long long)(z > 0.0f) << cl;
    }
    Ap[oidx] = bits;
}

// ---------------- the hot kernel: binary 3x3 conv via XNOR-popcount ----------------
// Thread = one output pixel; loops all 256 couts with weights in smem (broadcast LDS).
__global__ __launch_bounds__(448, 1)
void conv_bin_k(const unsigned long long* __restrict__ Xp,
                const unsigned long long* __restrict__ Wp,
                const int* __restrict__ corr,
                short* __restrict__ S) {
    extern __shared__ unsigned long long smem[];
    unsigned long long* sW = smem;                 // 9*256*4 = 9216 u64
    int* sC = (int*)(smem + 9 * C_ * NW_);         // 9*256 int
    int tid = threadIdx.x;
    for (int i = tid; i < 9 * C_ * NW_; i += 448) sW[i] = Wp[i];
    for (int i = tid; i < 9 * C_;       i += 448) sC[i] = corr[i];
    __syncthreads();

    int n  = blockIdx.y;
    int oy = blockIdx.x * 8 + (tid / W_);
    int ox = tid % W_;

    // load 3x3 neighborhood bitplanes (36 u64) into registers
    ulonglong2 xa[9], xb[9];
    #pragma unroll
    for (int ky = 0; ky < 3; ++ky)
        #pragma unroll
        for (int kx = 0; kx < 3; ++kx) {
            const ulonglong2* p = (const ulonglong2*)
                &Xp[(((size_t)n * PH_ + oy + ky) * PW_ + ox + kx) * NW_];
            xa[ky * 3 + kx] = p[0];
            xb[ky * 3 + kx] = p[1];
        }

    int rt = (oy == 0) ? 0 : ((oy == H_ - 1) ? 2 : 1);
    int ct = (ox == 0) ? 0 : ((ox == W_ - 1) ? 2 : 1);
    const int* csum = &sC[(rt * 3 + ct) * C_];

    size_t outbase = (((size_t)n * C_) * H_ + oy) * W_ + ox;
    for (int c = 0; c < C_; ++c) {
        int acc = 0;
        #pragma unroll
        for (int t = 0; t < 9; ++t) {
            const ulonglong2* wp2 = (const ulonglong2*)&sW[((size_t)t * C_ + c) * NW_];
            ulonglong2 w0 = wp2[0], w1 = wp2[1];
            acc += __popcll(xa[t].x ^ w0.x) + __popcll(xa[t].y ^ w0.y)
                 + __popcll(xb[t].x ^ w1.x) + __popcll(xb[t].y ^ w1.y);
        }
        int sval = 2304 - 2 * acc - csum[c];       // exact integer conv sum
        S[outbase + (size_t)c * PIX_] = (short)sval;
    }
}

// per-channel exact int64 stats of conv sums
__global__ void stats_k(const short* __restrict__ S, long long* sum, long long* sumsq) {
    int c = blockIdx.x, n = blockIdx.y;
    const short* p = S + ((size_t)n * C_ + c) * PIX_;
    int s = 0, q = 0;
    for (int i = threadIdx.x; i < PIX_; i += 128) { int v = p[i]; s += v; q += v * v; }
    #pragma unroll
    for (int o = 16; o; o >>= 1) {
        s += __shfl_down_sync(0xffffffffu, s, o);
        q += __shfl_down_sync(0xffffffffu, q, o);
    }
    __shared__ int ss[4], qq[4];
    int w = threadIdx.x >> 5, l = threadIdx.x & 31;
    if (l == 0) { ss[w] = s; qq[w] = q; }
    __syncthreads();
    if (threadIdx.x == 0) {
        long long S0 = 0, Q0 = 0;
        for (int i = 0; i < 4; ++i) { S0 += ss[i]; Q0 += qq[i]; }
        atomicAdd((unsigned long long*)&sum[c],   (unsigned long long)S0);
        atomicAdd((unsigned long long*)&sumsq[c], (unsigned long long)Q0);
    }
}

// fold BN (training-mode, eps=1e-5) + 0.5 conv scale into per-channel affine (a,b)
__global__ void bnparams_k(const long long* __restrict__ sum, const long long* __restrict__ sumsq,
                           const float* __restrict__ gamma, const float* __restrict__ beta,
                           float* __restrict__ a, float* __restrict__ b) {
    int c = threadIdx.x;
    const double M = (double)M_;
    double mS = (double)sum[c] / M;
    double vS = (double)sumsq[c] / M - mS * mS;
    double m = 0.5 * mS;               // y = 0.5*S
    double v = 0.25 * vS;
    double r = 1.0 / sqrt(v + 1e-5);
    double g = (double)gamma[c];
    a[c] = (float)(0.5 * r * g);
    b[c] = (float)((double)beta[c] - m * r * g);
}

// final: out = clip(a2[c]*S2 + b2[c] + x, -1, 1), vectorized by 4 (3136 % 4 == 0)
__global__ void final_k(const short* __restrict__ S2,
                        const float* __restrict__ a, const float* __restrict__ b,
                        const float* __restrict__ x, float* __restrict__ out) {
    size_t i = (size_t)blockIdx.x * blockDim.x + threadIdx.x;
    size_t base = i * 4;
    if (base >= (size_t)TOT_) return;
    int c = (int)((base / PIX_) % C_);
    float av = __ldg(&a[c]), bv = __ldg(&b[c]);
    short4 sv = *(const short4*)(S2 + base);
    float4 xv = *(const float4*)(x + base);
    float4 o;
    o.x = fminf(1.f, fmaxf(-1.f, av * (float)sv.x + bv + xv.x));
    o.y = fminf(1.f, fmaxf(-1.f, av * (float)sv.y + bv + xv.y));
    o.z = fminf(1.f, fmaxf(-1.f, av * (float)sv.z + bv + xv.z));
    o.w = fminf(1.f, fmaxf(-1.f, av * (float)sv.w + bv + xv.w));
    *(float4*)(out + base) = o;
}

// ---------------- launch ----------------
extern "C" void kernel_launch(void* const* d_in, const int* in_sizes, int n_in,
                              void* d_out, int out_size) {
    const float* x  = (const float*)d_in[0];
    const float* w1 = (const float*)d_in[1];
    const float* g1 = (const float*)d_in[2];
    const float* b1 = (const float*)d_in[3];
    const float* w2 = (const float*)d_in[4];
    const float* g2 = (const float*)d_in[5];
    const float* b2 = (const float*)d_in[6];
    float* out = (float*)d_out;

    // resolve device-global scratch pointers
    void *pXp, *pAp, *pW1, *pW2, *pc1, *pc2, *pS1, *pS2;
    void *psum1, *psq1, *psum2, *psq2, *pa1, *pb1, *pa2, *pb2;
    cudaGetSymbolAddress(&pXp, g_Xp);   cudaGetSymbolAddress(&pAp, g_Ap);
    cudaGetSymbolAddress(&pW1, g_W1);   cudaGetSymbolAddress(&pW2, g_W2);
    cudaGetSymbolAddress(&pc1, g_c1);   cudaGetSymbolAddress(&pc2, g_c2);
    cudaGetSymbolAddress(&pS1, g_S1);   cudaGetSymbolAddress(&pS2, g_S2);
    cudaGetSymbolAddress(&psum1, g_sum1); cudaGetSymbolAddress(&psq1, g_sq1);
    cudaGetSymbolAddress(&psum2, g_sum2); cudaGetSymbolAddress(&psq2, g_sq2);
    cudaGetSymbolAddress(&pa1, g_a1);   cudaGetSymbolAddress(&pb1, g_b1);
    cudaGetSymbolAddress(&pa2, g_a2);   cudaGetSymbolAddress(&pb2, g_b2);

    const int convSmem = 9 * C_ * NW_ * 8 + 9 * C_ * 4;   // 82944 B
    cudaFuncSetAttribute(conv_bin_k, cudaFuncAttributeMaxDynamicSharedMemorySize, convSmem);

    zero_stats_k<<<1, 256>>>();
    pack_w_k<<<9, 256>>>(w1, (unsigned long long*)pW1);
    pack_w_k<<<9, 256>>>(w2, (unsigned long long*)pW2);
    corr_w_k<<<1, 256>>>((const unsigned long long*)pW1, (int*)pc1);
    corr_w_k<<<1, 256>>>((const unsigned long long*)pW2, (int*)pc2);

    pack_x_k<<<dim3(PH_, N_), dim3(PW_, NW_)>>>(x, (unsigned long long*)pXp);

    conv_bin_k<<<dim3(H_ / 8, N_), 448, convSmem>>>(
        (const unsigned long long*)pXp, (const unsigned long long*)pW1,
        (const int*)pc1, (short*)pS1);

    stats_k<<<dim3(C_, N_), 128>>>((const short*)pS1, (long long*)psum1, (long long*)psq1);
    bnparams_k<<<1, 256>>>((const long long*)psum1, (const long long*)psq1, g1, b1,
                           (float*)pa1, (float*)pb1);

    thresh_pack_k<<<dim3(PH_, N_), dim3(PW_, NW_)>>>(
        (const short*)pS1, (const float*)pa1, (const float*)pb1, (unsigned long long*)pAp);

    conv_bin_k<<<dim3(H_ / 8, N_), 448, convSmem>>>(
        (const unsigned long long*)pAp, (const unsigned long long*)pW2,
        (const int*)pc2, (short*)pS2);

    stats_k<<<dim3(C_, N_), 128>>>((const short*)pS2, (long long*)psum2, (long long*)psq2);
    bnparams_k<<<1, 256>>>((const long long*)psum2, (const long long*)psq2, g2, b2,
                           (float*)pa2, (float*)pb2);

    final_k<<<(TOT_ / 4 + 255) / 256, 256>>>(
        (const short*)pS2, (const float*)pa2, (const float*)pb2, x, out);
}